// round 6
// baseline (speedup 1.0000x reference)
#include <cuda_runtime.h>
#include <cuda_bf16.h>
#include <math.h>

// Problem constants
#define N_NODES   500000
#define HIDDEN    256
#define NCLASS    104
#define AUXD      2
#define NGRAPH    2048
#define GRAPHX    128
#define DIN       (NCLASS + AUXD)   // 106
#define BN_EPS    1e-5f

// Kernel A tiling
#define BM        128      // nodes per block
#define KC        16       // k chunk
#define TA        224      // threads (16 m-groups x 14 n-groups)
#define AST       132      // As row stride (padded: 16B aligned, low bank conflict)
#define BST       112      // Bs row stride (C padded to 112)

typedef unsigned long long u64;

// Scratch: per-graph pooled readout accumulator
__device__ float g_pool[NGRAPH * NCLASS];

// ---------------- packed f32x2 helpers ----------------
__device__ __forceinline__ void fma2(u64& d, u64 a, u64 b, u64 c) {
    asm("fma.rn.f32x2 %0, %1, %2, %3;" : "=l"(d) : "l"(a), "l"(b), "l"(c));
}
__device__ __forceinline__ u64 pack_dup(float v) {
    u64 r;
    asm("mov.b64 %0, {%1, %1};" : "=l"(r) : "f"(v));
    return r;
}
__device__ __forceinline__ void unpack2(u64 v, float& lo, float& hi) {
    asm("mov.b64 {%0, %1}, %2;" : "=f"(lo), "=f"(hi) : "l"(v));
}

__device__ __forceinline__ float sigmoidf_(float x) {
    return 1.0f / (1.0f + expf(-x));
}

// ---------------- zero the pool scratch ----------------
__global__ void zero_pool_kernel() {
    int i = blockIdx.x * blockDim.x + threadIdx.x;
    if (i < NGRAPH * NCLASS) g_pool[i] = 0.0f;
}

// ---------------- Kernel A: nodewise gated readout + segment pooling ----------------
__global__ __launch_bounds__(TA, 2)
void nodewise_kernel(const float* __restrict__ init_states,
                     const float* __restrict__ fin_states,
                     const int*   __restrict__ gids,
                     const float* __restrict__ Wg, const float* __restrict__ bg,
                     const float* __restrict__ Wt, const float* __restrict__ bt)
{
    extern __shared__ float sm[];
    float* As = sm;                       // KC * AST
    float* Bs = As + KC * AST;            // KC * BST
    float* Gs = Bs + KC * BST;            // BM * NCLASS
    int*   sg = (int*)(Gs + BM * NCLASS); // BM

    const int tid = threadIdx.x;
    const int n0  = blockIdx.x * BM;

    // stage graph ids for this node tile
    for (int i = tid; i < BM; i += TA) {
        int n = n0 + i;
        sg[i] = (n < N_NODES) ? gids[n] : -1;
    }

    const int tn = tid % 14;          // class group
    const int tm = tid / 14;          // node group
    const int cb = tn * 8;            // class base (>=104 for tn==13: waste lane)
    const int mb = tm * 8;            // node base

    u64 acc[4][8];

    // ================= Pass G: gate logits, K = 512 ([init|fin] @ Wg) =================
    #pragma unroll
    for (int i = 0; i < 4; i++)
        #pragma unroll
        for (int j = 0; j < 8; j++) acc[i][j] = 0ull;

    for (int kc = 0; kc < 2 * HIDDEN; kc += KC) {
        __syncthreads();
        const float* src = (kc < HIDDEN) ? init_states : fin_states;
        const int kbase  = (kc < HIDDEN) ? kc : (kc - HIDDEN);
        for (int idx = tid; idx < KC * BM; idx += TA) {
            int m = idx >> 4, k = idx & 15;
            int n = n0 + m;
            As[k * AST + m] = (n < N_NODES) ? src[n * HIDDEN + kbase + k] : 0.0f;
        }
        for (int idx = tid; idx < KC * BST; idx += TA) {
            int c = idx % BST, k = idx / BST;
            Bs[k * BST + c] = (c < NCLASS) ? Wg[(kc + k) * NCLASS + c] : 0.0f;
        }
        __syncthreads();
        #pragma unroll
        for (int k = 0; k < KC; k++) {
            const u64* ap = (const u64*)&As[k * AST + mb];   // 8B aligned
            u64 pa0 = ap[0], pa1 = ap[1], pa2 = ap[2], pa3 = ap[3];
            float4 b0 = *(const float4*)&Bs[k * BST + cb];
            float4 b1 = *(const float4*)&Bs[k * BST + cb + 4];
            float bv[8] = {b0.x, b0.y, b0.z, b0.w, b1.x, b1.y, b1.z, b1.w};
            #pragma unroll
            for (int j = 0; j < 8; j++) {
                u64 bb = pack_dup(bv[j]);
                fma2(acc[0][j], pa0, bb, acc[0][j]);
                fma2(acc[1][j], pa1, bb, acc[1][j]);
                fma2(acc[2][j], pa2, bb, acc[2][j]);
                fma2(acc[3][j], pa3, bb, acc[3][j]);
            }
        }
    }

    // epilogue G: sigmoid(logit + bg) -> Gs[m][c]
    if (cb < NCLASS) {
        #pragma unroll
        for (int j = 0; j < 8; j++) {
            const int c = cb + j;
            const float bias = bg[c];
            #pragma unroll
            for (int i = 0; i < 4; i++) {
                float v0, v1;
                unpack2(acc[i][j], v0, v1);
                Gs[(mb + 2 * i)     * NCLASS + c] = sigmoidf_(v0 + bias);
                Gs[(mb + 2 * i + 1) * NCLASS + c] = sigmoidf_(v1 + bias);
            }
        }
    }

    // ================= Pass T: transform, K = 256 (fin @ Wt) =================
    #pragma unroll
    for (int i = 0; i < 4; i++)
        #pragma unroll
        for (int j = 0; j < 8; j++) acc[i][j] = 0ull;

    for (int kc = 0; kc < HIDDEN; kc += KC) {
        __syncthreads();
        for (int idx = tid; idx < KC * BM; idx += TA) {
            int m = idx >> 4, k = idx & 15;
            int n = n0 + m;
            As[k * AST + m] = (n < N_NODES) ? fin_states[n * HIDDEN + kc + k] : 0.0f;
        }
        for (int idx = tid; idx < KC * BST; idx += TA) {
            int c = idx % BST, k = idx / BST;
            Bs[k * BST + c] = (c < NCLASS) ? Wt[(kc + k) * NCLASS + c] : 0.0f;
        }
        __syncthreads();
        #pragma unroll
        for (int k = 0; k < KC; k++) {
            const u64* ap = (const u64*)&As[k * AST + mb];
            u64 pa0 = ap[0], pa1 = ap[1], pa2 = ap[2], pa3 = ap[3];
            float4 b0 = *(const float4*)&Bs[k * BST + cb];
            float4 b1 = *(const float4*)&Bs[k * BST + cb + 4];
            float bv[8] = {b0.x, b0.y, b0.z, b0.w, b1.x, b1.y, b1.z, b1.w};
            #pragma unroll
            for (int j = 0; j < 8; j++) {
                u64 bb = pack_dup(bv[j]);
                fma2(acc[0][j], pa0, bb, acc[0][j]);
                fma2(acc[1][j], pa1, bb, acc[1][j]);
                fma2(acc[2][j], pa2, bb, acc[2][j]);
                fma2(acc[3][j], pa3, bb, acc[3][j]);
            }
        }
    }

    // epilogue T: nodewise = gate * (t + bt) -> Gs[m][c]
    if (cb < NCLASS) {
        #pragma unroll
        for (int j = 0; j < 8; j++) {
            const int c = cb + j;
            const float bias = bt[c];
            #pragma unroll
            for (int i = 0; i < 4; i++) {
                float v0, v1;
                unpack2(acc[i][j], v0, v1);
                Gs[(mb + 2 * i)     * NCLASS + c] *= (v0 + bias);
                Gs[(mb + 2 * i + 1) * NCLASS + c] *= (v1 + bias);
            }
        }
    }
    __syncthreads();

    // ================= segmented pooling (nodes sorted by graph id) =================
    if (tid < 2 * NCLASS) {
        const int c   = tid % NCLASS;
        const int seg = tid / NCLASS;       // 0 or 1: rows [0,64) / [64,128)
        int r   = seg * 64;
        int cur = sg[r];
        float s = 0.0f;
        #pragma unroll 4
        for (int i = 0; i < 64; i++, r++) {
            int g = sg[r];
            if (g != cur) {
                if (cur >= 0) atomicAdd(&g_pool[cur * NCLASS + c], s);
                s = 0.0f;
                cur = g;
            }
            if (g >= 0) s += Gs[r * NCLASS + c];
        }
        if (cur >= 0) atomicAdd(&g_pool[cur * NCLASS + c], s);
    }
}

// ---------------- Kernel B: per-graph BN + MLP ----------------
__global__ __launch_bounds__(GRAPHX)
void graph_mlp_kernel(const float* __restrict__ aux,
                      const float* __restrict__ bn_gamma, const float* __restrict__ bn_beta,
                      const float* __restrict__ bn_mean,  const float* __restrict__ bn_var,
                      const float* __restrict__ W1, const float* __restrict__ b1,
                      const float* __restrict__ W2, const float* __restrict__ b2,
                      float* __restrict__ out)
{
    __shared__ float norm[DIN];
    __shared__ float h[GRAPHX];
    const int g   = blockIdx.x;
    const int tid = threadIdx.x;

    if (tid < DIN) {
        float ext = (tid < NCLASS) ? g_pool[g * NCLASS + tid]
                                   : aux[g * AUXD + (tid - NCLASS)];
        norm[tid] = (ext - bn_mean[tid]) * rsqrtf(bn_var[tid] + BN_EPS) * bn_gamma[tid]
                    + bn_beta[tid];
    }
    __syncthreads();

    // hidden: 106 -> 128
    {
        float acc = b1[tid];
        #pragma unroll 2
        for (int d = 0; d < DIN; d++)
            acc = fmaf(norm[d], __ldg(&W1[d * GRAPHX + tid]), acc);
        h[tid] = fmaxf(acc, 0.0f);
    }
    __syncthreads();

    // logits: 128 -> 104
    if (tid < NCLASS) {
        float acc = b2[tid];
        #pragma unroll 4
        for (int j = 0; j < GRAPHX; j++)
            acc = fmaf(h[j], __ldg(&W2[j * NCLASS + tid]), acc);
        out[g * NCLASS + tid] = acc;
    }
}

// ---------------- launch ----------------
extern "C" void kernel_launch(void* const* d_in, const int* in_sizes, int n_in,
                              void* d_out, int out_size)
{
    const float* init_states = (const float*)d_in[0];
    const float* fin_states  = (const float*)d_in[1];
    const float* aux         = (const float*)d_in[2];
    const int*   gids        = (const int*)  d_in[3];
    // d_in[4] = num_graphs (unused; compile-time constant)
    const float* Wg = (const float*)d_in[5];
    const float* bg = (const float*)d_in[6];
    const float* Wt = (const float*)d_in[7];
    const float* bt = (const float*)d_in[8];
    const float* bn_gamma = (const float*)d_in[9];
    const float* bn_beta  = (const float*)d_in[10];
    const float* bn_mean  = (const float*)d_in[11];
    const float* bn_var   = (const float*)d_in[12];
    const float* W1 = (const float*)d_in[13];
    const float* b1 = (const float*)d_in[14];
    const float* W2 = (const float*)d_in[15];
    const float* b2 = (const float*)d_in[16];
    float* out = (float*)d_out;

    const int smem_bytes = (KC * AST + KC * BST + BM * NCLASS) * (int)sizeof(float)
                         + BM * (int)sizeof(int);
    // Unconditional (no static guards — harness rule); idempotent and capture-safe.
    cudaFuncSetAttribute(nodewise_kernel,
                         cudaFuncAttributeMaxDynamicSharedMemorySize, smem_bytes);

    // 1) zero the pool scratch
    {
        int total = NGRAPH * NCLASS;
        zero_pool_kernel<<<(total + 255) / 256, 256>>>();
    }
    // 2) nodewise gated readout + pooling
    {
        int nblk = (N_NODES + BM - 1) / BM;
        nodewise_kernel<<<nblk, TA, smem_bytes>>>(init_states, fin_states, gids,
                                                  Wg, bg, Wt, bt);
    }
    // 3) per-graph BN + MLP
    graph_mlp_kernel<<<NGRAPH, GRAPHX>>>(aux, bn_gamma, bn_beta, bn_mean, bn_var,
                                         W1, b1, W2, b2, out);
}

// round 10
// speedup vs baseline: 1.0826x; 1.0826x over previous
#include <cuda_runtime.h>
#include <cuda_bf16.h>
#include <stdint.h>
#include <math.h>

// Problem constants
#define N_NODES   500000
#define HIDDEN    256
#define NCLASS    104
#define AUXD      2
#define NGRAPH    2048
#define GRAPHX    128
#define DIN       (NCLASS + AUXD)   // 106
#define BN_EPS    1e-5f

// Kernel A tiling
#define BM        128               // nodes per block
#define KC        16                // k chunk
#define NCH       (HIDDEN / KC)     // 16 chunks
#define CPAD      112               // classes padded
#define TB        448               // threads: 16 m-groups x 28 c-groups

typedef unsigned long long u64;

// Scratch: per-graph pooled readout accumulator
__device__ float g_pool[NGRAPH * NCLASS];

// ---------------- packed f32x2 helpers ----------------
__device__ __forceinline__ void fma2(u64& d, u64 a, u64 b, u64 c) {
    asm("fma.rn.f32x2 %0, %1, %2, %3;" : "=l"(d) : "l"(a), "l"(b), "l"(c));
}
__device__ __forceinline__ u64 pack_dup(float v) {
    u64 r;
    asm("mov.b64 %0, {%1, %1};" : "=l"(r) : "f"(v));
    return r;
}
__device__ __forceinline__ void unpack2(u64 v, float& lo, float& hi) {
    asm("mov.b64 {%0, %1}, %2;" : "=f"(lo), "=f"(hi) : "l"(v));
}
__device__ __forceinline__ float sigmoidf_(float x) {
    return 1.0f / (1.0f + expf(-x));
}
__device__ __forceinline__ void cp16(uint32_t dst, const void* src, int srcsz) {
    asm volatile("cp.async.cg.shared.global [%0], [%1], 16, %2;"
                 :: "r"(dst), "l"(src), "r"(srcsz));
}

// SMEM float offsets (staging region; Gs is a union over it)
#define OFF_ASI   0                      // [2][BM][KC]   = 4096 floats
#define OFF_ASF   4096                   // [2][BM][KC]   = 4096
#define OFF_BGI   8192                   // [2][KC][CPAD] = 3584
#define OFF_BGF   11776                  // [2][KC][CPAD] = 3584
#define OFF_BT    15360                  // [2][KC][CPAD] = 3584
#define STAGE_FLTS 18944
#define GS_FLTS   (BM * CPAD)            // 14336 (aliases staging)
#define SMEM_FLTS STAGE_FLTS             // max(18944, 14336)
#define SMEM_BYTES (SMEM_FLTS * 4 + BM * 4)

// ---------------- zero the pool scratch ----------------
__global__ void zero_pool_kernel() {
    int i = blockIdx.x * blockDim.x + threadIdx.x;
    if (i < NGRAPH * NCLASS) g_pool[i] = 0.0f;
}

// ---------------- Kernel A: fused gated readout + segment pooling ----------------
__global__ __launch_bounds__(TB, 1)
void nodewise_kernel(const float* __restrict__ init_states,
                     const float* __restrict__ fin_states,
                     const int*   __restrict__ gids,
                     const float* __restrict__ Wg, const float* __restrict__ bg,
                     const float* __restrict__ Wt, const float* __restrict__ bt)
{
    extern __shared__ float sm[];
    int* sg = (int*)(sm + SMEM_FLTS);     // [BM]
    const int tid = threadIdx.x;
    const int n0  = blockIdx.x * BM;

    const uint32_t smem_u32 = (uint32_t)__cvta_generic_to_shared(sm);

    // stage graph ids
    for (int i = tid; i < BM; i += TB) {
        int n = n0 + i;
        sg[i] = (n < N_NODES) ? gids[n] : -1;
    }

    // ---- per-chunk async staging (A: 1024 16B units, B: 3*416 units) ----
    auto stage_chunk = [&](int c) {
        const int buf = c & 1;
        const int kc  = c * KC;
        for (int u = tid; u < 1024 + 3 * 416; u += TB) {
            if (u < 1024) {
                int which = u >> 9;             // 0=init, 1=fin
                int m     = (u >> 2) & 127;
                int kq    = u & 3;              // 16B quarter of the 16-float row
                int n     = n0 + m;
                int nc    = (n < N_NODES) ? n : 0;
                const float* src = (which ? fin_states : init_states)
                                   + (size_t)nc * HIDDEN + kc + kq * 4;
                int sz = (n < N_NODES) ? 16 : 0;    // zero-fill OOB rows
                uint32_t dst = smem_u32
                    + ((which ? OFF_ASF : OFF_ASI) + buf * BM * KC + m * KC + kq * 4) * 4;
                cp16(dst, src, sz);
            } else {
                int j    = u - 1024;
                int tile = j / 416;
                int jj   = j % 416;
                int r    = jj / 26;             // k row within chunk
                int q    = jj % 26;             // 16B chunk along classes (26*4=104)
                const float* src;
                int offb;
                if (tile == 0)      { src = Wg + (size_t)(kc + r) * NCLASS + q * 4;          offb = OFF_BGI; }
                else if (tile == 1) { src = Wg + (size_t)(HIDDEN + kc + r) * NCLASS + q * 4; offb = OFF_BGF; }
                else                { src = Wt + (size_t)(kc + r) * NCLASS + q * 4;          offb = OFF_BT;  }
                uint32_t dst = smem_u32 + (offb + buf * KC * CPAD + r * CPAD + q * 4) * 4;
                cp16(dst, src, 16);
            }
        }
        asm volatile("cp.async.commit_group;");
    };

    const int tm = tid / 28;            // 0..15  -> node group
    const int tn = tid % 28;            // 0..27  -> class-pair group
    const int mb = tm * 8;
    const int cb = tn * 4;              // classes [cb, cb+4); cb>=104 -> padding lanes

    u64 accG[8][2], accT[8][2];
    #pragma unroll
    for (int i = 0; i < 8; i++) {
        accG[i][0] = accG[i][1] = 0ull;
        accT[i][0] = accT[i][1] = 0ull;
    }

    // prologue: 2 chunks in flight
    stage_chunk(0);
    stage_chunk(1);

    for (int c = 0; c < NCH; c++) {
        if (c >= NCH - 2) asm volatile("cp.async.wait_group 0;");
        else              asm volatile("cp.async.wait_group 1;");
        __syncthreads();

        const int buf = c & 1;
        const float* aI  = sm + OFF_ASI + buf * BM * KC + mb * KC;
        const float* aF  = sm + OFF_ASF + buf * BM * KC + mb * KC;
        const float* bgi = sm + OFF_BGI + buf * KC * CPAD;
        const float* bgf = sm + OFF_BGF + buf * KC * CPAD;
        const float* btt = sm + OFF_BT  + buf * KC * CPAD;

        #pragma unroll 4
        for (int kk = 0; kk < KC; kk++) {
            ulonglong2 bG_i = *(const ulonglong2*)&bgi[kk * CPAD + cb];
            ulonglong2 bG_f = *(const ulonglong2*)&bgf[kk * CPAD + cb];
            ulonglong2 bT   = *(const ulonglong2*)&btt[kk * CPAD + cb];
            #pragma unroll
            for (int i = 0; i < 8; i++) {
                u64 pi = pack_dup(aI[i * KC + kk]);
                u64 pf = pack_dup(aF[i * KC + kk]);
                fma2(accG[i][0], pi, bG_i.x, accG[i][0]);
                fma2(accG[i][0], pf, bG_f.x, accG[i][0]);
                fma2(accG[i][1], pi, bG_i.y, accG[i][1]);
                fma2(accG[i][1], pf, bG_f.y, accG[i][1]);
                fma2(accT[i][0], pf, bT.x,   accT[i][0]);
                fma2(accT[i][1], pf, bT.y,   accT[i][1]);
            }
        }
        __syncthreads();
        if (c + 2 < NCH) stage_chunk(c + 2);
    }

    // ---- epilogue: nodewise = sigmoid(gate + bg) * (t + bt) -> Gs (aliases staging) ----
    float* Gs = sm;                     // [BM][CPAD]
    if (cb < NCLASS) {
        float4 bgv = *(const float4*)&bg[cb];
        float4 btv = *(const float4*)&bt[cb];
        float bgA[4] = {bgv.x, bgv.y, bgv.z, bgv.w};
        float btA[4] = {btv.x, btv.y, btv.z, btv.w};
        #pragma unroll
        for (int i = 0; i < 8; i++) {
            #pragma unroll
            for (int p = 0; p < 2; p++) {
                float g0, g1, t0, t1;
                unpack2(accG[i][p], g0, g1);
                unpack2(accT[i][p], t0, t1);
                float r0 = sigmoidf_(g0 + bgA[2 * p])     * (t0 + btA[2 * p]);
                float r1 = sigmoidf_(g1 + bgA[2 * p + 1]) * (t1 + btA[2 * p + 1]);
                Gs[(mb + i) * CPAD + cb + 2 * p]     = r0;
                Gs[(mb + i) * CPAD + cb + 2 * p + 1] = r1;
            }
        }
    }
    __syncthreads();

    // ---- segmented pooling (nodes sorted by graph id) ----
    if (tid < 2 * NCLASS) {
        const int cc  = tid % NCLASS;
        const int seg = tid / NCLASS;       // rows [0,64) / [64,128)
        int r   = seg * 64;
        int cur = sg[r];
        float s = 0.0f;
        #pragma unroll 4
        for (int i = 0; i < 64; i++, r++) {
            int g = sg[r];
            if (g != cur) {
                if (cur >= 0) atomicAdd(&g_pool[cur * NCLASS + cc], s);
                s = 0.0f;
                cur = g;
            }
            if (g >= 0) s += Gs[r * CPAD + cc];
        }
        if (cur >= 0) atomicAdd(&g_pool[cur * NCLASS + cc], s);
    }
}

// ---------------- Kernel B: per-graph BN + MLP ----------------
__global__ __launch_bounds__(GRAPHX)
void graph_mlp_kernel(const float* __restrict__ aux,
                      const float* __restrict__ bn_gamma, const float* __restrict__ bn_beta,
                      const float* __restrict__ bn_mean,  const float* __restrict__ bn_var,
                      const float* __restrict__ W1, const float* __restrict__ b1,
                      const float* __restrict__ W2, const float* __restrict__ b2,
                      float* __restrict__ out)
{
    __shared__ float norm[DIN];
    __shared__ float h[GRAPHX];
    const int g   = blockIdx.x;
    const int tid = threadIdx.x;

    if (tid < DIN) {
        float ext = (tid < NCLASS) ? g_pool[g * NCLASS + tid]
                                   : aux[g * AUXD + (tid - NCLASS)];
        norm[tid] = (ext - bn_mean[tid]) * rsqrtf(bn_var[tid] + BN_EPS) * bn_gamma[tid]
                    + bn_beta[tid];
    }
    __syncthreads();

    {
        float acc = b1[tid];
        #pragma unroll 2
        for (int d = 0; d < DIN; d++)
            acc = fmaf(norm[d], __ldg(&W1[d * GRAPHX + tid]), acc);
        h[tid] = fmaxf(acc, 0.0f);
    }
    __syncthreads();

    if (tid < NCLASS) {
        float acc = b2[tid];
        #pragma unroll 4
        for (int j = 0; j < GRAPHX; j++)
            acc = fmaf(h[j], __ldg(&W2[j * NCLASS + tid]), acc);
        out[g * NCLASS + tid] = acc;
    }
}

// ---------------- launch ----------------
extern "C" void kernel_launch(void* const* d_in, const int* in_sizes, int n_in,
                              void* d_out, int out_size)
{
    const float* init_states = (const float*)d_in[0];
    const float* fin_states  = (const float*)d_in[1];
    const float* aux         = (const float*)d_in[2];
    const int*   gids        = (const int*)  d_in[3];
    // d_in[4] = num_graphs (compile-time constant)
    const float* Wg = (const float*)d_in[5];
    const float* bg = (const float*)d_in[6];
    const float* Wt = (const float*)d_in[7];
    const float* bt = (const float*)d_in[8];
    const float* bn_gamma = (const float*)d_in[9];
    const float* bn_beta  = (const float*)d_in[10];
    const float* bn_mean  = (const float*)d_in[11];
    const float* bn_var   = (const float*)d_in[12];
    const float* W1 = (const float*)d_in[13];
    const float* b1 = (const float*)d_in[14];
    const float* W2 = (const float*)d_in[15];
    const float* b2 = (const float*)d_in[16];
    float* out = (float*)d_out;

    // Unconditional (no static guards); idempotent and capture-safe.
    cudaFuncSetAttribute(nodewise_kernel,
                         cudaFuncAttributeMaxDynamicSharedMemorySize, SMEM_BYTES);

    {
        int total = NGRAPH * NCLASS;
        zero_pool_kernel<<<(total + 255) / 256, 256>>>();
    }
    {
        int nblk = (N_NODES + BM - 1) / BM;
        nodewise_kernel<<<nblk, TB, SMEM_BYTES>>>(init_states, fin_states, gids,
                                                  Wg, bg, Wt, bt);
    }
    graph_mlp_kernel<<<NGRAPH, GRAPHX>>>(aux, bn_gamma, bn_beta, bn_mean, bn_var,
                                         W1, b1, W2, b2, out);
}

// round 13
// speedup vs baseline: 3.6113x; 3.3358x over previous
#include <cuda_runtime.h>
#include <cuda_bf16.h>
#include <stdint.h>
#include <math.h>

// ---------------- problem constants ----------------
#define N_NODES   500000
#define HIDDEN    256
#define NCLASS    104
#define AUXD      2
#define NGRAPH    2048
#define GRAPHX    128
#define DIN       (NCLASS + AUXD)
#define BN_EPS    1e-5f

// ---------------- main-kernel tiling ----------------
#define BM        128               // nodes per block
#define TB        256               // 8 warps, each owns M=16 rows
#define NT        13                // 13 n8 tiles = 104 classes exactly
#define KC        16                // K per chunk (2 k8 steps)
#define NCHUNK    (HIDDEN / KC)     // 16
#define AST       20                // A smem row stride (floats): frag loads conflict-free

// SMEM float offsets
#define A_FLTS    (BM * AST)                    // 2560 per array
#define OFF_A(buf, which) (((buf) * 2 + (which)) * A_FLTS)
#define B_CHUNK_U32 (3 * 2 * NT * 32 * 2)       // 4992 uint32 per chunk
#define OFF_B(buf)  (4 * A_FLTS + (buf) * B_CHUNK_U32)
#define SMEM_MAIN   ((4 * A_FLTS + 2 * B_CHUNK_U32) * 4)   // 80896 B
#define SMEM_BYTES  (SMEM_MAIN + 512)

// ---------------- device scratch ----------------
__device__ float g_pool[NGRAPH * NCLASS];
// tf32 weights packed in b-fragment order: [chunk][mat(3:Wgi,Wgf,Wt)][s(2)][j(13)][lane(32)][2]
__device__ uint32_t g_wb[NCHUNK][B_CHUNK_U32];

// ---------------- helpers ----------------
__device__ __forceinline__ float sigmoidf_(float x) {
    return 1.0f / (1.0f + expf(-x));
}
__device__ __forceinline__ void cp16(uint32_t dst, const void* src, int srcsz) {
    asm volatile("cp.async.cg.shared.global [%0], [%1], 16, %2;"
                 :: "r"(dst), "l"(src), "r"(srcsz));
}
__device__ __forceinline__ void cp16f(uint32_t dst, const void* src) {
    asm volatile("cp.async.cg.shared.global [%0], [%1], 16;"
                 :: "r"(dst), "l"(src));
}
__device__ __forceinline__ uint32_t f2tf(float x) {
    uint32_t u;
    asm("cvt.rna.tf32.f32 %0, %1;" : "=r"(u) : "f"(x));
    return u;
}
__device__ __forceinline__ void mma_tf32(float* d, const uint32_t* a, uint2 b) {
    asm volatile(
        "mma.sync.aligned.m16n8k8.row.col.f32.tf32.tf32.f32 "
        "{%0,%1,%2,%3}, {%4,%5,%6,%7}, {%8,%9}, {%0,%1,%2,%3};"
        : "+f"(d[0]), "+f"(d[1]), "+f"(d[2]), "+f"(d[3])
        : "r"(a[0]), "r"(a[1]), "r"(a[2]), "r"(a[3]), "r"(b.x), "r"(b.y));
}

// ---------------- zero the pool scratch ----------------
__global__ void zero_pool_kernel() {
    int i = blockIdx.x * blockDim.x + threadIdx.x;
    if (i < NGRAPH * NCLASS) g_pool[i] = 0.0f;
}

// ---------------- weight prep: pack tf32 b-fragments ----------------
// b0 = B[k8 = lane%4][n = j*8 + lane/4], b1 = B[k8 = lane%4 + 4][n]
__global__ void prep_weights_kernel(const float* __restrict__ Wg,
                                    const float* __restrict__ Wt) {
    int idx = blockIdx.x * blockDim.x + threadIdx.x;
    const int total = NCHUNK * B_CHUNK_U32;     // 79872
    if (idx >= total) return;
    int e = idx;
    int p = e & 1;  e >>= 1;
    int t = e & 31; e >>= 5;
    int j = e % NT; e /= NT;
    int s = e & 1;  e >>= 1;
    int mat = e % 3; e /= 3;
    int c = e;                                   // chunk
    int k = c * KC + s * 8 + (t & 3) + p * 4;    // 0..255
    int n = j * 8 + (t >> 2);                    // 0..103
    float v;
    if (mat == 0)      v = Wg[(size_t)k * NCLASS + n];
    else if (mat == 1) v = Wg[(size_t)(HIDDEN + k) * NCLASS + n];
    else               v = Wt[(size_t)k * NCLASS + n];
    g_wb[c][(((mat * 2 + s) * NT + j) * 32 + t) * 2 + p] = f2tf(v);
}

// ---------------- Kernel A: HMMA gated readout + segment pooling ----------------
__global__ __launch_bounds__(TB, 1)
void nodewise_kernel(const float* __restrict__ init_states,
                     const float* __restrict__ fin_states,
                     const int*   __restrict__ gids,
                     const float* __restrict__ bg,
                     const float* __restrict__ bt)
{
    extern __shared__ float sm[];
    uint32_t* smB = (uint32_t*)sm;
    int* sg = (int*)((char*)sm + SMEM_MAIN);    // [BM]
    const uint32_t smem_u32 = (uint32_t)__cvta_generic_to_shared(sm);

    const int tid  = threadIdx.x;
    const int w    = tid / 32;
    const int lane = tid % 32;
    const int n0   = blockIdx.x * BM;

    for (int i = tid; i < BM; i += TB) {
        int n = n0 + i;
        sg[i] = (n < N_NODES) ? gids[n] : -1;
    }

    // ---- async staging of one chunk ----
    auto stage = [&](int c) {
        const int buf = c & 1;
        // A: 1024 float4 tasks (init+fin, 128 rows x 4 quarters)
        #pragma unroll
        for (int i = 0; i < 4; i++) {
            int task  = tid + i * TB;
            int which = task >> 9;
            int rem   = task & 511;
            int m     = rem >> 2;
            int kq    = rem & 3;
            int n     = n0 + m;
            int nc    = (n < N_NODES) ? n : 0;
            const float* src = (which ? fin_states : init_states)
                               + (size_t)nc * HIDDEN + c * KC + kq * 4;
            uint32_t dst = smem_u32 + (OFF_A(buf, which) + m * AST + kq * 4) * 4;
            cp16(dst, src, (n < N_NODES) ? 16 : 0);
        }
        // B: 1248 float4 (pre-packed fragments, verbatim)
        for (int u = tid; u < B_CHUNK_U32 / 4; u += TB) {
            cp16f(smem_u32 + (OFF_B(buf) + u * 4) * 4, &g_wb[c][u * 4]);
        }
        asm volatile("cp.async.commit_group;");
    };

    float ga[NT][4], ta[NT][4];
    #pragma unroll
    for (int j = 0; j < NT; j++) {
        #pragma unroll
        for (int q = 0; q < 4; q++) { ga[j][q] = 0.0f; ta[j][q] = 0.0f; }
    }

    stage(0);
    stage(1);

    const int g  = lane >> 2;
    const int t4 = lane & 3;

    for (int c = 0; c < NCHUNK; c++) {
        if (c >= NCHUNK - 2) asm volatile("cp.async.wait_group 0;");
        else                 asm volatile("cp.async.wait_group 1;");
        __syncthreads();

        const int buf = c & 1;
        const float* Ai = sm + OFF_A(buf, 0);
        const float* Af = sm + OFF_A(buf, 1);
        const uint2* Bp = (const uint2*)(smB + OFF_B(buf));

        #pragma unroll
        for (int s = 0; s < 2; s++) {
            const int row = w * 16 + g;
            const int col = s * 8 + t4;
            uint32_t ai[4], af[4];
            ai[0] = f2tf(Ai[(row)     * AST + col]);
            ai[1] = f2tf(Ai[(row + 8) * AST + col]);
            ai[2] = f2tf(Ai[(row)     * AST + col + 4]);
            ai[3] = f2tf(Ai[(row + 8) * AST + col + 4]);
            af[0] = f2tf(Af[(row)     * AST + col]);
            af[1] = f2tf(Af[(row + 8) * AST + col]);
            af[2] = f2tf(Af[(row)     * AST + col + 4]);
            af[3] = f2tf(Af[(row + 8) * AST + col + 4]);
            #pragma unroll
            for (int j = 0; j < NT; j++) {
                uint2 bgi = Bp[((0 * 2 + s) * NT + j) * 32 + lane];
                uint2 bgf = Bp[((2     + s) * NT + j) * 32 + lane];
                uint2 btt = Bp[((4     + s) * NT + j) * 32 + lane];
                mma_tf32(ga[j], ai, bgi);
                mma_tf32(ga[j], af, bgf);
                mma_tf32(ta[j], af, btt);
            }
        }
        __syncthreads();
        if (c + 2 < NCHUNK) stage(c + 2);
    }
    __syncthreads();    // all warps done reading smem before Gs overwrite

    // ---- epilogue: nodewise = sigmoid(gate + bg) * (t + bt) -> Gs ----
    float* Gs = sm;     // [BM][NCLASS], aliases staging buffers
    #pragma unroll
    for (int j = 0; j < NT; j++) {
        #pragma unroll
        for (int h = 0; h < 2; h++) {
            int row = w * 16 + g + h * 8;
            int c0  = j * 8 + 2 * t4;
            float gv0 = ga[j][2 * h]     + __ldg(&bg[c0]);
            float gv1 = ga[j][2 * h + 1] + __ldg(&bg[c0 + 1]);
            float tv0 = ta[j][2 * h]     + __ldg(&bt[c0]);
            float tv1 = ta[j][2 * h + 1] + __ldg(&bt[c0 + 1]);
            Gs[row * NCLASS + c0]     = sigmoidf_(gv0) * tv0;
            Gs[row * NCLASS + c0 + 1] = sigmoidf_(gv1) * tv1;
        }
    }
    __syncthreads();

    // ---- segmented pooling (nodes sorted by graph id) ----
    if (tid < 2 * NCLASS) {
        const int cc  = tid % NCLASS;
        const int seg = tid / NCLASS;
        int r   = seg * 64;
        int cur = sg[r];
        float s = 0.0f;
        #pragma unroll 4
        for (int i = 0; i < 64; i++, r++) {
            int gg = sg[r];
            if (gg != cur) {
                if (cur >= 0) atomicAdd(&g_pool[cur * NCLASS + cc], s);
                s = 0.0f;
                cur = gg;
            }
            if (gg >= 0) s += Gs[r * NCLASS + cc];
        }
        if (cur >= 0) atomicAdd(&g_pool[cur * NCLASS + cc], s);
    }
}

// ---------------- Kernel B: per-graph BN + MLP ----------------
__global__ __launch_bounds__(GRAPHX)
void graph_mlp_kernel(const float* __restrict__ aux,
                      const float* __restrict__ bn_gamma, const float* __restrict__ bn_beta,
                      const float* __restrict__ bn_mean,  const float* __restrict__ bn_var,
                      const float* __restrict__ W1, const float* __restrict__ b1,
                      const float* __restrict__ W2, const float* __restrict__ b2,
                      float* __restrict__ out)
{
    __shared__ float norm[DIN];
    __shared__ float h[GRAPHX];
    const int g   = blockIdx.x;
    const int tid = threadIdx.x;

    if (tid < DIN) {
        float ext = (tid < NCLASS) ? g_pool[g * NCLASS + tid]
                                   : aux[g * AUXD + (tid - NCLASS)];
        norm[tid] = (ext - bn_mean[tid]) * rsqrtf(bn_var[tid] + BN_EPS) * bn_gamma[tid]
                    + bn_beta[tid];
    }
    __syncthreads();

    {
        float acc = b1[tid];
        #pragma unroll 2
        for (int d = 0; d < DIN; d++)
            acc = fmaf(norm[d], __ldg(&W1[d * GRAPHX + tid]), acc);
        h[tid] = fmaxf(acc, 0.0f);
    }
    __syncthreads();

    if (tid < NCLASS) {
        float acc = b2[tid];
        #pragma unroll 4
        for (int j = 0; j < GRAPHX; j++)
            acc = fmaf(h[j], __ldg(&W2[j * NCLASS + tid]), acc);
        out[g * NCLASS + tid] = acc;
    }
}

// ---------------- launch ----------------
extern "C" void kernel_launch(void* const* d_in, const int* in_sizes, int n_in,
                              void* d_out, int out_size)
{
    const float* init_states = (const float*)d_in[0];
    const float* fin_states  = (const float*)d_in[1];
    const float* aux         = (const float*)d_in[2];
    const int*   gids        = (const int*)  d_in[3];
    // d_in[4] = num_graphs (compile-time constant)
    const float* Wg = (const float*)d_in[5];
    const float* bg = (const float*)d_in[6];
    const float* Wt = (const float*)d_in[7];
    const float* bt = (const float*)d_in[8];
    const float* bn_gamma = (const float*)d_in[9];
    const float* bn_beta  = (const float*)d_in[10];
    const float* bn_mean  = (const float*)d_in[11];
    const float* bn_var   = (const float*)d_in[12];
    const float* W1 = (const float*)d_in[13];
    const float* b1 = (const float*)d_in[14];
    const float* W2 = (const float*)d_in[15];
    const float* b2 = (const float*)d_in[16];
    float* out = (float*)d_out;

    // Unconditional; idempotent and capture-safe.
    cudaFuncSetAttribute(nodewise_kernel,
                         cudaFuncAttributeMaxDynamicSharedMemorySize, SMEM_BYTES);

    {
        int total = NGRAPH * NCLASS;
        zero_pool_kernel<<<(total + 255) / 256, 256>>>();
    }
    {
        int total = NCHUNK * B_CHUNK_U32;
        prep_weights_kernel<<<(total + 255) / 256, 256>>>(Wg, Wt);
    }
    {
        int nblk = (N_NODES + BM - 1) / BM;
        nodewise_kernel<<<nblk, TB, SMEM_BYTES>>>(init_states, fin_states, gids, bg, bt);
    }
    graph_mlp_kernel<<<NGRAPH, GRAPHX>>>(aux, bn_gamma, bn_beta, bn_mean, bn_var,
                                         W1, b1, W2, b2, out);
}